// round 5
// baseline (speedup 1.0000x reference)
#include <cuda_runtime.h>
#include <cstdint>

// MTF_68461778698457: Markov Transition Field
// x: (N=4096, C=4, L=256) f32  ->  out: (N, C, 65, 65) f32
// One CTA (256 threads) per (n,c) row.
//
// Numerics ladder (rel_err):
//   div.rn / exact floor          : 0.0730
//   raw rcp.approx + mul (2-op)   : 0.0280   (== my ptxas div.full expansion)
// This round: classical div.full Newton expansion (JAX-ptxas form):
//   r0 = rcp.approx(b); e = fma(-b,r0,1); r1 = fma(r0,e,r0); q = mul.rn(a,r1)

constexpr int L    = 256;
constexpr int NB   = 65;
constexpr int NB2  = NB * NB;   // 4225

// Hand-coded div.full.f32 with one Newton-Raphson refinement of MUFU.RCP.
// Entire sequence pinned in PTX so ptxas cannot re-expand it differently.
__device__ __forceinline__ float div_full_newton(float a, float b)
{
    float q;
    asm("{\n\t"
        ".reg .f32 r0, e, r1;\n\t"
        "rcp.approx.f32 r0, %2;\n\t"
        "fma.rn.f32 e, %2, r0, 0fBF800000;\n\t"   // e' = b*r0 - 1
        "neg.f32 e, e;\n\t"                        // e  = 1 - b*r0
        "fma.rn.f32 r1, r0, e, r0;\n\t"            // r1 = r0 + r0*e
        "mul.rn.f32 %0, %1, r1;\n\t"
        "}"
        : "=f"(q) : "f"(a), "f"(b));
    return q;
}

__global__ __launch_bounds__(256)
void mtf_kernel(const float* __restrict__ x, float* __restrict__ out)
{
    __shared__ unsigned long long skey[L];   // 2 KB
    __shared__ int sbin[L];                  // 1 KB
    __shared__ int scnt[NB2];                // 16.9 KB
    __shared__ int s_start, s_end;

    const int row = blockIdx.x;
    const int t   = threadIdx.x;

    const float v = x[(size_t)row * L + t];

    if (t == 0) { s_start = L; s_end = -1; }
    #pragma unroll
    for (int i = t; i < NB2; i += 256) scnt[i] = 0;
    __syncthreads();

    if (v != 0.0f) {            // -0.0 counts as zero, same as reference x != 0
        atomicMin(&s_start, t);
        atomicMax(&s_end, t);
    }
    __syncthreads();

    const int start = s_start;
    const int end   = s_end;
    const bool has   = (end >= start);
    const bool valid = has && (t >= start) && (t <= end);
    const int  vl    = has ? (end - start + 1) : 1;

    // Order-preserving 64-bit key: monotonic uint map of the float in the high
    // word, index in the low word. A single u64 '<' reproduces the stable
    // argsort rank (ties broken by index). Invalid -> max key (ref uses +inf).
    unsigned int u = __float_as_uint(v);
    unsigned int o = (u & 0x80000000u) ? ~u : (u | 0x80000000u);
    unsigned long long key = valid
        ? (((unsigned long long)o << 32) | (unsigned int)t)
        : 0xFFFFFFFFFFFFFFFFull;
    skey[t] = key;
    __syncthreads();

    int b = 0;
    if (valid) {
        int rank = 0;
        #pragma unroll 8
        for (int j = 0; j < L; j++) {
            rank += (skey[j] < key) ? 1 : 0;
        }
        // bin = trunc( divfull_newton(rank, vl) * 65 ), clip to [0,64]
        float q  = div_full_newton((float)rank, (float)vl);
        float rb = __fmul_rn(q, 65.0f);
        int bi = (int)rb;                      // cvt.rzi.s32.f32 (trunc)
        bi = bi < 0 ? 0 : bi;
        bi = bi > (NB - 1) ? (NB - 1) : bi;
        b = bi;
    }
    sbin[t] = b;
    __syncthreads();

    // Transition histogram: pairs (t, t+1), both valid  <=>  start <= t < end.
    if (valid && t < end) {
        atomicAdd(&scnt[sbin[t] * NB + sbin[t + 1]], 1);
    }
    __syncthreads();

    // Normalize with the same division flavor, store coalesced.
    int norm = vl - 1;
    if (norm < 1) norm = 1;
    const float fnorm = (float)norm;
    float* o_ptr = out + (size_t)row * NB2;
    #pragma unroll
    for (int i = t; i < NB2; i += 256) {
        o_ptr[i] = div_full_newton((float)scnt[i], fnorm);
    }
}

extern "C" void kernel_launch(void* const* d_in, const int* in_sizes, int n_in,
                              void* d_out, int out_size)
{
    const float* x = (const float*)d_in[0];
    float* out = (float*)d_out;
    const int nrows = in_sizes[0] / L;   // N*C = 16384
    mtf_kernel<<<nrows, 256>>>(x, out);
}

// round 6
// speedup vs baseline: 1.8615x; 1.8615x over previous
#include <cuda_runtime.h>
#include <cstdint>

// MTF_68461778698457: Markov Transition Field
// x: (N=4096, C=4, L=256) f32  ->  out: (N, C, 65, 65) f32
// One CTA (256 threads) per (n,c) row.
//
// Numerics (locked in, rel_err == 0.0): reference division is the classical
// div.full.f32 Newton expansion:
//   r0 = rcp.approx(b); e = 1 - b*r0; r1 = fma(r0,e,r0); q = mul.rn(a,r1)
// We hoist r1 (depends only on b) and multiply — bit-identical.
//
// Rank: bitonic sort of 64-bit keys (order-mapped float << 32 | index).
// Sorted position == stable-argsort rank, identical to the O(L^2) count.

constexpr int L    = 256;
constexpr int NB   = 65;
constexpr int NB2  = NB * NB;   // 4225

// Refined reciprocal: the div.full.f32 Newton chain minus the final multiply.
__device__ __forceinline__ float refined_rcp(float b)
{
    float r;
    asm("{\n\t"
        ".reg .f32 r0, e;\n\t"
        "rcp.approx.f32 r0, %1;\n\t"
        "fma.rn.f32 e, %1, r0, 0fBF800000;\n\t"   // e' = b*r0 - 1
        "neg.f32 e, e;\n\t"                        // e  = 1 - b*r0
        "fma.rn.f32 %0, r0, e, %0;\n\t"            // (dummy use avoided below)
        "}"
        : "+f"(r) : "f"(b));
    return r;
}

// NOTE: the asm above must compute r1 = fma(r0, e, r0); rewrite cleanly:
__device__ __forceinline__ float refined_rcp2(float b)
{
    float r;
    asm("{\n\t"
        ".reg .f32 r0, e;\n\t"
        "rcp.approx.f32 r0, %1;\n\t"
        "fma.rn.f32 e, %1, r0, 0fBF800000;\n\t"   // e' = b*r0 - 1
        "neg.f32 e, e;\n\t"                        // e  = 1 - b*r0
        "fma.rn.f32 %0, r0, e, r0;\n\t"            // r1 = r0 + r0*e
        "}"
        : "=f"(r) : "f"(b));
    return r;
}

__global__ __launch_bounds__(256)
void mtf_kernel(const float* __restrict__ x, float* __restrict__ out)
{
    __shared__ unsigned long long skey[L];   // 2 KB (sort exchange buffer)
    __shared__ int sbin[L];                  // 1 KB
    __shared__ int scnt[NB2];                // 16.9 KB
    __shared__ int s_start, s_end;

    const int row = blockIdx.x;
    const int t   = threadIdx.x;

    const float v = x[(size_t)row * L + t];

    if (t == 0) { s_start = L; s_end = -1; }
    #pragma unroll
    for (int i = t; i < NB2; i += 256) scnt[i] = 0;
    __syncthreads();

    if (v != 0.0f) {            // -0.0 counts as zero, same as reference
        atomicMin(&s_start, t);
        atomicMax(&s_end, t);
    }
    __syncthreads();

    const int start = s_start;
    const int end   = s_end;
    const bool has   = (end >= start);
    const bool validme = has && (t >= start) && (t <= end);
    const int  vl    = has ? (end - start + 1) : 1;

    // 64-bit key: monotonic uint map of float in high word, index in low word.
    // Single u64 '<' == stable argsort order (ties by index). Invalid -> max.
    unsigned int u = __float_as_uint(v);
    unsigned int o = (u & 0x80000000u) ? ~u : (u | 0x80000000u);
    unsigned long long mine = validme
        ? (((unsigned long long)o << 32) | (unsigned int)t)
        : 0xFFFFFFFFFFFFFFFFull;

    // ---- Bitonic sort, thread t owns one element --------------------------
    #pragma unroll
    for (int k = 2; k <= 256; k <<= 1) {
        // cross-warp stages (j >= 32) via smem
        #pragma unroll
        for (int j = k >> 1; j >= 32; j >>= 1) {
            skey[t] = mine;
            __syncthreads();
            unsigned long long other = skey[t ^ j];
            bool keepmin  = ((t & j) == 0) == ((t & k) == 0);
            bool takeoth  = (other < mine) == keepmin;
            mine = takeoth ? other : mine;
            __syncthreads();
        }
        // intra-warp stages (j < 32) via shfl.bfly, no barriers
        #pragma unroll
        for (int j = ((k >> 1) < 32 ? (k >> 1) : 16); j > 0; j >>= 1) {
            unsigned long long other = __shfl_xor_sync(0xffffffffu, mine, j);
            bool keepmin  = ((t & j) == 0) == ((t & k) == 0);
            bool takeoth  = (other < mine) == keepmin;
            mine = takeoth ? other : mine;
        }
    }
    // Thread t now holds the t-th smallest key; rank of that element == t.
    // Valid elements occupy sorted positions [0, vl).

    // ---- Bin + scatter ----------------------------------------------------
    if (has && t < vl) {
        const float rinv = refined_rcp2((float)vl);           // r1(vl)
        float q  = __fmul_rn((float)t, rinv);                 // div.full(t,vl)
        float rb = __fmul_rn(q, 65.0f);
        int bi = (int)rb;                                     // trunc
        bi = bi < 0 ? 0 : bi;
        bi = bi > (NB - 1) ? (NB - 1) : bi;
        sbin[(unsigned int)(mine & 0xffffffffu)] = bi;        // scatter to orig idx
    }
    __syncthreads();

    // ---- Transition histogram: pairs (t, t+1), start <= t < end -----------
    if (has && t >= start && t < end) {
        atomicAdd(&scnt[sbin[t] * NB + sbin[t + 1]], 1);
    }
    __syncthreads();

    // ---- Normalize + store (coalesced), hoisted refined reciprocal --------
    int norm = vl - 1;
    if (norm < 1) norm = 1;
    const float rnorm = refined_rcp2((float)norm);            // r1(norm)
    float* o_ptr = out + (size_t)row * NB2;
    #pragma unroll
    for (int i = t; i < NB2; i += 256) {
        o_ptr[i] = __fmul_rn((float)scnt[i], rnorm);          // == div.full
    }
}

extern "C" void kernel_launch(void* const* d_in, const int* in_sizes, int n_in,
                              void* d_out, int out_size)
{
    const float* x = (const float*)d_in[0];
    float* out = (float*)d_out;
    const int nrows = in_sizes[0] / L;   // N*C = 16384
    mtf_kernel<<<nrows, 256>>>(x, out);
}

// round 7
// speedup vs baseline: 2.0048x; 1.0770x over previous
#include <cuda_runtime.h>
#include <cstdint>

// MTF_68461778698457: Markov Transition Field
// x: (N=4096, C=4, L=256) f32  ->  out: (N, C, 65, 65) f32
//
// One WARP per row (8 elements/thread, register bitonic sort), 8 rows per
// 256-thread CTA. Phase 2: per-row transition histogram + normalized store.
//
// Numerics (locked, rel_err == 0.0): reference division is the classical
// div.full.f32 Newton expansion; we hoist the refined reciprocal r1(b)
// (depends only on b) and mul.rn — bit-identical to div.full(a,b).

constexpr int L    = 256;
constexpr int NB   = 65;
constexpr int NB2  = NB * NB;        // 4225
constexpr int RPC  = 8;              // rows per CTA (one per warp)

__device__ __forceinline__ float refined_rcp(float b)
{
    float r;
    asm("{\n\t"
        ".reg .f32 r0, e;\n\t"
        "rcp.approx.f32 r0, %1;\n\t"
        "fma.rn.f32 e, %1, r0, 0fBF800000;\n\t"   // e' = b*r0 - 1
        "neg.f32 e, e;\n\t"                        // e  = 1 - b*r0
        "fma.rn.f32 %0, r0, e, r0;\n\t"            // r1 = r0 + r0*e
        "}"
        : "=f"(r) : "f"(b));
    return r;
}

__global__ __launch_bounds__(256)
void mtf_kernel(const float* __restrict__ x, float* __restrict__ out)
{
    __shared__ unsigned int  scnt[NB2];            // 16.9 KB histogram (reused)
    __shared__ unsigned char sbin[RPC][L];         // 2 KB bins per row
    __shared__ int s_first[RPC], s_end[RPC], s_vl[RPC];

    const int t    = threadIdx.x;
    const int w    = t >> 5;          // warp id = row within CTA
    const int lane = t & 31;
    const long long rowg = (long long)blockIdx.x * RPC + w;

    // ---- Phase 1: per-warp load, range scan, register bitonic sort --------
    {
        const float* xr = x + rowg * L + lane * 8;
        float4 va = *(const float4*)(xr);
        float4 vb = *(const float4*)(xr + 4);
        float v[8] = { va.x, va.y, va.z, va.w, vb.x, vb.y, vb.z, vb.w };

        // first/last nonzero index (warp-wide)
        int locF = 256, locE = -1;
        #pragma unroll
        for (int i = 0; i < 8; i++) {
            int idx = lane * 8 + i;
            if (v[i] != 0.0f) {
                if (idx < locF) locF = idx;
                if (idx > locE) locE = idx;
            }
        }
        const int first = __reduce_min_sync(0xffffffffu, locF);
        const int last  = __reduce_max_sync(0xffffffffu, locE);
        const bool has  = (last >= first);
        const int  vl   = has ? (last - first + 1) : 1;

        // 64-bit keys: (order-mapped float << 32) | index; invalid -> max.
        unsigned long long key[8];
        #pragma unroll
        for (int i = 0; i < 8; i++) {
            int idx = lane * 8 + i;
            unsigned int u = __float_as_uint(v[i]);
            unsigned int o = (u & 0x80000000u) ? ~u : (u | 0x80000000u);
            bool valid = has && (idx >= first) && (idx <= last);
            key[i] = valid ? ((((unsigned long long)o) << 32) | (unsigned)idx)
                           : 0xFFFFFFFFFFFFFFFFull;
        }

        // compare-exchange on register pair (a,b); ascending iff asc
        #define CE(a, b, asc)                                                \
            do {                                                             \
                if ((key[a] > key[b]) == (asc)) {                            \
                    unsigned long long _tmp = key[a];                        \
                    key[a] = key[b]; key[b] = _tmp;                          \
                }                                                            \
            } while (0)

        // shfl compare-exchange stage: partner lane^off, direction asc
        #define STAGE_SHFL(off, asc)                                         \
            do {                                                             \
                bool _lower = (lane & (off)) == 0;                           \
                bool _keepMin = ((asc) == _lower);                           \
                _Pragma("unroll")                                            \
                for (int _i = 0; _i < 8; _i++) {                             \
                    unsigned long long _o =                                  \
                        __shfl_xor_sync(0xffffffffu, key[_i], (off));        \
                    bool _take = (_o < key[_i]) == _keepMin;                 \
                    key[_i] = _take ? _o : key[_i];                          \
                }                                                            \
            } while (0)

        // local merge of size 8 (j = 4,2,1), single direction
        #define LOCAL3(asc)                                                  \
            do {                                                             \
                CE(0,4,asc); CE(1,5,asc); CE(2,6,asc); CE(3,7,asc);          \
                CE(0,2,asc); CE(1,3,asc); CE(4,6,asc); CE(5,7,asc);          \
                CE(0,1,asc); CE(2,3,asc); CE(4,5,asc); CE(6,7,asc);          \
            } while (0)

        // ---- bitonic network over 256 elements (e = 8*lane + i) ----
        // k=2
        CE(0,1,true); CE(2,3,false); CE(4,5,true); CE(6,7,false);
        // k=4
        CE(0,2,true); CE(1,3,true);  CE(4,6,false); CE(5,7,false);
        CE(0,1,true); CE(2,3,true);  CE(4,5,false); CE(6,7,false);
        // k=8 : direction depends on lane bit 0
        { bool a8 = (lane & 1) == 0; LOCAL3(a8); }
        // k=16
        { bool a = (lane & 2) == 0; STAGE_SHFL(1, a); LOCAL3(a); }
        // k=32
        { bool a = (lane & 4) == 0; STAGE_SHFL(2, a); STAGE_SHFL(1, a); LOCAL3(a); }
        // k=64
        { bool a = (lane & 8) == 0; STAGE_SHFL(4, a); STAGE_SHFL(2, a);
          STAGE_SHFL(1, a); LOCAL3(a); }
        // k=128
        { bool a = (lane & 16) == 0; STAGE_SHFL(8, a); STAGE_SHFL(4, a);
          STAGE_SHFL(2, a); STAGE_SHFL(1, a); LOCAL3(a); }
        // k=256 (final ascending merge)
        { STAGE_SHFL(16, true); STAGE_SHFL(8, true); STAGE_SHFL(4, true);
          STAGE_SHFL(2, true); STAGE_SHFL(1, true); LOCAL3(true); }

        // Thread holds sorted positions [8*lane, 8*lane+8); rank = 8*lane+i.
        // Valid elements occupy ranks [0, vl).
        const float rinv = refined_rcp((float)vl);   // r1(vl): div.full hoist
        #pragma unroll
        for (int i = 0; i < 8; i++) {
            int r = lane * 8 + i;
            if (r < vl) {
                float q  = __fmul_rn((float)r, rinv);      // == div.full(r,vl)
                float rb = __fmul_rn(q, 65.0f);
                int bi = (int)rb;                          // trunc
                bi = bi > (NB - 1) ? (NB - 1) : bi;
                int orig = (int)(key[i] & 0xffu);
                sbin[w][orig] = (unsigned char)bi;
            }
        }
        if (lane == 0) { s_first[w] = first; s_end[w] = last; s_vl[w] = vl; }

        #undef CE
        #undef STAGE_SHFL
        #undef LOCAL3
    }
    __syncthreads();

    // ---- Phase 2: per-row histogram + normalized store --------------------
    for (int r = 0; r < RPC; r++) {
        // zero histogram (vectorized: 4225 = 4*1056 + 1)
        int4* c4 = (int4*)scnt;
        #pragma unroll
        for (int i = t; i < 1056; i += 256) c4[i] = make_int4(0, 0, 0, 0);
        if (t == 0) scnt[4224] = 0u;
        __syncthreads();

        // transitions: start <= t < end
        {
            const int f = s_first[r], e = s_end[r];
            if (t >= f && t < e) {
                int b0 = sbin[r][t];
                int b1 = sbin[r][t + 1];
                atomicAdd(&scnt[b0 * NB + b1], 1u);
            }
        }
        __syncthreads();

        // normalize + store: out row base misaligned by (row*4225)%4 floats
        {
            int nrm = s_vl[r] - 1; if (nrm < 1) nrm = 1;
            const float rnorm = refined_rcp((float)nrm);   // r1(norm)
            const size_t p0 = ((size_t)blockIdx.x * RPC + r) * (size_t)NB2;
            float* op = out + p0;
            const int lead = (int)((4 - (p0 & 3)) & 3);
            const int rem  = NB2 - lead;
            const int nv   = rem >> 2;
            const int tail = rem & 3;

            if (t < lead)
                op[t] = __fmul_rn((float)scnt[t], rnorm);
            for (int i = t; i < nv; i += 256) {
                int f = lead + 4 * i;
                float4 wv;
                wv.x = __fmul_rn((float)scnt[f + 0], rnorm);
                wv.y = __fmul_rn((float)scnt[f + 1], rnorm);
                wv.z = __fmul_rn((float)scnt[f + 2], rnorm);
                wv.w = __fmul_rn((float)scnt[f + 3], rnorm);
                *(float4*)(op + f) = wv;
            }
            if (t < tail) {
                int f = lead + 4 * nv + t;
                op[f] = __fmul_rn((float)scnt[f], rnorm);
            }
        }
        __syncthreads();
    }
}

extern "C" void kernel_launch(void* const* d_in, const int* in_sizes, int n_in,
                              void* d_out, int out_size)
{
    const float* x = (const float*)d_in[0];
    float* out = (float*)d_out;
    const int nrows = in_sizes[0] / L;       // N*C = 16384 (divisible by 8)
    mtf_kernel<<<nrows / RPC, 256>>>(x, out);
}